// round 1
// baseline (speedup 1.0000x reference)
#include <cuda_runtime.h>

// Problem constants
#define T_    4
#define B_    32
#define C_    512
#define HW_   256
#define NH    8
#define HD    64
#define SLICE 4194304      // B*C*HW = one time slice
#define TOTAL 16777216     // T*B*C*HW
#define CN    131072       // C*HW per (t,b)

// Scratch (static device globals; allocation-free per harness rules)
__device__ float g_xs[TOTAL];
__device__ float g_q [TOTAL];
__device__ float g_k [TOTAL];
__device__ float g_v [TOTAL];
__device__ float g_x2[TOTAL];
__device__ float g_attn[2 * B_ * NH * HD * HD];   // [chunk][b][h][dh][de]

// ---------------------------------------------------------------------------
// K1: shortcut LIF on x -> binary spikes (stored as fp32 for GEMM simplicity)
// v' = v + (x - v)/2 ; spike if v' >= 1 ; hard reset to 0
// ---------------------------------------------------------------------------
__global__ void lif_in_kernel(const float* __restrict__ x, float* __restrict__ xs)
{
    int i = blockIdx.x * blockDim.x + threadIdx.x;
    if (i >= SLICE) return;
    float v = 0.f;
#pragma unroll
    for (int t = 0; t < T_; t++) {
        float xv = x[(size_t)t * SLICE + i];
        v = v + (xv - v) * 0.5f;
        float s = (v >= 1.0f) ? 1.0f : 0.0f;
        xs[(size_t)t * SLICE + i] = s;
        if (s != 0.f) v = 0.f;
    }
}

// ---------------------------------------------------------------------------
// K3: in-place LIF (threshold parameterized)
// ---------------------------------------------------------------------------
__global__ void lif_ip_kernel(float* __restrict__ y, float vth)
{
    int i = blockIdx.x * blockDim.x + threadIdx.x;
    if (i >= SLICE) return;
    float v = 0.f;
#pragma unroll
    for (int t = 0; t < T_; t++) {
        float xv = y[(size_t)t * SLICE + i];
        v = v + (xv - v) * 0.5f;
        float s = (v >= vth) ? 1.0f : 0.0f;
        y[(size_t)t * SLICE + i] = s;
        if (s != 0.f) v = 0.f;
    }
}

// ---------------------------------------------------------------------------
// K2: batched conv1x1 + BN:  dst[tb, m, n] = (sum_k W[m,k]*src[tb,k,n])*scale[m]+bias[m]
// Tile: 64(M) x 64(N) x 16(K), 256 threads, 4x4 micro-tile per thread.
// grid = (HW/64=4, C/64=8, T*B=128)
// ---------------------------------------------------------------------------
__global__ void gemm_qkv_kernel(const float* __restrict__ Wm,
                                const float* __restrict__ src,
                                float* __restrict__ dst,
                                const float* __restrict__ scale,
                                const float* __restrict__ bias)
{
    __shared__ float As[64][17];   // [m][k], padded
    __shared__ float Bs[16][64];   // [k][n]

    int tb = blockIdx.z;
    const float* S = src + (size_t)tb * CN;
    float* D = dst + (size_t)tb * CN;
    int m0 = blockIdx.y * 64;
    int n0 = blockIdx.x * 64;
    int tid = threadIdx.x;
    int tx = tid & 15, ty = tid >> 4;

    float acc[4][4] = {};

    for (int k0 = 0; k0 < C_; k0 += 16) {
        // load A: 64 rows x 16 cols of W
        {
            int row = tid >> 2;
            int col = (tid & 3) * 4;
            float4 w = *(const float4*)&Wm[(size_t)(m0 + row) * C_ + k0 + col];
            As[row][col + 0] = w.x; As[row][col + 1] = w.y;
            As[row][col + 2] = w.z; As[row][col + 3] = w.w;
        }
        // load B: 16 rows x 64 cols of spikes
        {
            int row = tid >> 4;
            int col = (tid & 15) * 4;
            *(float4*)&Bs[row][col] = *(const float4*)&S[(size_t)(k0 + row) * HW_ + n0 + col];
        }
        __syncthreads();
#pragma unroll
        for (int kk = 0; kk < 16; kk++) {
            float a[4], bv[4];
#pragma unroll
            for (int i = 0; i < 4; i++) a[i] = As[ty * 4 + i][kk];
#pragma unroll
            for (int j = 0; j < 4; j++) bv[j] = Bs[kk][tx * 4 + j];
#pragma unroll
            for (int i = 0; i < 4; i++)
#pragma unroll
                for (int j = 0; j < 4; j++) acc[i][j] += a[i] * bv[j];
        }
        __syncthreads();
    }

#pragma unroll
    for (int i = 0; i < 4; i++) {
        int m = m0 + ty * 4 + i;
        float sc = scale[m], bi = bias[m];
#pragma unroll
        for (int j = 0; j < 4; j++) {
            D[(size_t)m * HW_ + n0 + tx * 4 + j] = acc[i][j] * sc + bi;
        }
    }
}

// ---------------------------------------------------------------------------
// K6: proj conv + conv_bias + BN + identity add, writes directly to d_out[0..TOTAL)
// ---------------------------------------------------------------------------
__global__ void gemm_proj_kernel(const float* __restrict__ Wm,
                                 const float* __restrict__ src,
                                 float* __restrict__ out,
                                 const float* __restrict__ scale,
                                 const float* __restrict__ bias,
                                 const float* __restrict__ cbias,
                                 const float* __restrict__ identity)
{
    __shared__ float As[64][17];
    __shared__ float Bs[16][64];

    int tb = blockIdx.z;
    const float* S = src + (size_t)tb * CN;
    float* D = out + (size_t)tb * CN;
    const float* ID = identity + (size_t)tb * CN;
    int m0 = blockIdx.y * 64;
    int n0 = blockIdx.x * 64;
    int tid = threadIdx.x;
    int tx = tid & 15, ty = tid >> 4;

    float acc[4][4] = {};

    for (int k0 = 0; k0 < C_; k0 += 16) {
        {
            int row = tid >> 2;
            int col = (tid & 3) * 4;
            float4 w = *(const float4*)&Wm[(size_t)(m0 + row) * C_ + k0 + col];
            As[row][col + 0] = w.x; As[row][col + 1] = w.y;
            As[row][col + 2] = w.z; As[row][col + 3] = w.w;
        }
        {
            int row = tid >> 4;
            int col = (tid & 15) * 4;
            *(float4*)&Bs[row][col] = *(const float4*)&S[(size_t)(k0 + row) * HW_ + n0 + col];
        }
        __syncthreads();
#pragma unroll
        for (int kk = 0; kk < 16; kk++) {
            float a[4], bv[4];
#pragma unroll
            for (int i = 0; i < 4; i++) a[i] = As[ty * 4 + i][kk];
#pragma unroll
            for (int j = 0; j < 4; j++) bv[j] = Bs[kk][tx * 4 + j];
#pragma unroll
            for (int i = 0; i < 4; i++)
#pragma unroll
                for (int j = 0; j < 4; j++) acc[i][j] += a[i] * bv[j];
        }
        __syncthreads();
    }

#pragma unroll
    for (int i = 0; i < 4; i++) {
        int m = m0 + ty * 4 + i;
        float sc = scale[m], bi = bias[m], cb = cbias[m];
#pragma unroll
        for (int j = 0; j < 4; j++) {
            size_t idx = (size_t)m * HW_ + n0 + tx * 4 + j;
            D[idx] = (acc[i][j] + cb) * sc + bi + ID[idx];
        }
    }
}

// ---------------------------------------------------------------------------
// K4: linear attention  attn[chunk,b,h,dh,de] = (1/16) * sum_{tc,n} k*v
// One CTA per (chunk,b,h): 64x64 output, K=512 tokens in 8 tiles of 64.
// ---------------------------------------------------------------------------
__global__ void attn_kernel(const float* __restrict__ ksp,
                            const float* __restrict__ vsp,
                            float* __restrict__ attn)
{
    __shared__ float ks[64 * 65];
    __shared__ float vs[64 * 65];

    int cbh = blockIdx.x;
    int h = cbh & 7;
    int b = (cbh >> 3) & 31;
    int chunk = cbh >> 8;
    int tid = threadIdx.x;
    int tx = tid & 15, ty = tid >> 4;

    float acc[4][4] = {};

    for (int st = 0; st < 8; st++) {
        int t = chunk * 2 + (st >> 2);
        int n0 = (st & 3) * 64;
        const float* kp = ksp + (size_t)t * SLICE + ((size_t)b * C_ + h * HD) * HW_ + n0;
        const float* vp = vsp + (size_t)t * SLICE + ((size_t)b * C_ + h * HD) * HW_ + n0;
        __syncthreads();
#pragma unroll
        for (int p = 0; p < 4; p++) {
            int row = p * 16 + (tid >> 4);
            int col = (tid & 15) * 4;
            float4 kq = *(const float4*)&kp[(size_t)row * HW_ + col];
            ks[row * 65 + col + 0] = kq.x; ks[row * 65 + col + 1] = kq.y;
            ks[row * 65 + col + 2] = kq.z; ks[row * 65 + col + 3] = kq.w;
            float4 vq = *(const float4*)&vp[(size_t)row * HW_ + col];
            vs[row * 65 + col + 0] = vq.x; vs[row * 65 + col + 1] = vq.y;
            vs[row * 65 + col + 2] = vq.z; vs[row * 65 + col + 3] = vq.w;
        }
        __syncthreads();
#pragma unroll 16
        for (int ss = 0; ss < 64; ss++) {
            float a[4], bv[4];
#pragma unroll
            for (int i = 0; i < 4; i++) a[i] = ks[(ty * 4 + i) * 65 + ss];
#pragma unroll
            for (int j = 0; j < 4; j++) bv[j] = vs[(tx * 4 + j) * 65 + ss];
#pragma unroll
            for (int i = 0; i < 4; i++)
#pragma unroll
                for (int j = 0; j < 4; j++) acc[i][j] += a[i] * bv[j];
        }
    }

    float* ap = attn + ((((size_t)chunk * B_ + b) * NH + h) * HD) * HD;
#pragma unroll
    for (int i = 0; i < 4; i++)
#pragma unroll
        for (int j = 0; j < 4; j++)
            ap[(ty * 4 + i) * HD + tx * 4 + j] = acc[i][j] * 0.0625f;
}

// ---------------------------------------------------------------------------
// K5: x2_pre[t,b,h*64+de,n] = sum_dh attn[chunk(t),b,h,dh,de] * q[t,b,h*64+dh,n]
// then LIF (vth=0.5) across t in registers, write spikes to g_x2.
// One CTA per (nblk, h, b): 64(de) x 64(n) tile for all 4 t.
// ---------------------------------------------------------------------------
__global__ void x2_lif_kernel(const float* __restrict__ qsp,
                              const float* __restrict__ attn,
                              float* __restrict__ x2)
{
    __shared__ float a_s[64 * 64];   // attn[dh][de] for current chunk
    __shared__ float q_s[64 * 64];   // q[dh][n] for current t

    int nblk = blockIdx.x, h = blockIdx.y, b = blockIdx.z;
    int n0 = nblk * 64;
    int tid = threadIdx.x;
    int tx = tid & 15, ty = tid >> 4;

    float acc[T_][4][4];
#pragma unroll
    for (int t = 0; t < T_; t++)
#pragma unroll
        for (int i = 0; i < 4; i++)
#pragma unroll
            for (int j = 0; j < 4; j++) acc[t][i][j] = 0.f;

#pragma unroll
    for (int t = 0; t < T_; t++) {
        int chunk = t >> 1;
        __syncthreads();
        if ((t & 1) == 0) {
            const float* ap = attn + ((((size_t)chunk * B_ + b) * NH + h) * HD) * HD;
#pragma unroll
            for (int p = 0; p < 4; p++) {
                int idx = p * 1024 + tid * 4;
                *(float4*)&a_s[idx] = *(const float4*)&ap[idx];
            }
        }
        const float* qp = qsp + (size_t)t * SLICE + ((size_t)b * C_ + h * HD) * HW_ + n0;
#pragma unroll
        for (int p = 0; p < 4; p++) {
            int row = p * 16 + (tid >> 4);
            int col = (tid & 15) * 4;
            *(float4*)&q_s[row * 64 + col] = *(const float4*)&qp[(size_t)row * HW_ + col];
        }
        __syncthreads();
#pragma unroll 16
        for (int kk = 0; kk < 64; kk++) {
            float a[4], bv[4];
#pragma unroll
            for (int i = 0; i < 4; i++) a[i] = a_s[kk * 64 + ty * 4 + i];
#pragma unroll
            for (int j = 0; j < 4; j++) bv[j] = q_s[kk * 64 + tx * 4 + j];
#pragma unroll
            for (int i = 0; i < 4; i++)
#pragma unroll
                for (int j = 0; j < 4; j++) acc[t][i][j] += a[i] * bv[j];
        }
    }

    // LIF over t (vth = 0.5), write spikes
#pragma unroll
    for (int i = 0; i < 4; i++) {
        int c = h * HD + ty * 4 + i;
#pragma unroll
        for (int j = 0; j < 4; j++) {
            int n = n0 + tx * 4 + j;
            float v = 0.f;
#pragma unroll
            for (int t = 0; t < T_; t++) {
                float xv = acc[t][i][j];
                v = v + (xv - v) * 0.5f;
                float s = (v >= 0.5f) ? 1.0f : 0.0f;
                x2[(size_t)t * SLICE + ((size_t)b * C_ + c) * HW_ + n] = s;
                if (s != 0.f) v = 0.f;
            }
        }
    }
}

// ---------------------------------------------------------------------------
// K7: v spikes transpose to output layout [T,B,h,N,hd]
// out[t,b,h,n,dh] = v_sp[t,b,h*64+dh,n]
// ---------------------------------------------------------------------------
__global__ void vtrans_kernel(const float* __restrict__ vsp, float* __restrict__ outv)
{
    __shared__ float tile[64][65];
    int nblk = blockIdx.x, h = blockIdx.y, tb = blockIdx.z;
    int t = tb >> 5, b = tb & 31;
    const float* src = vsp + (size_t)t * SLICE + ((size_t)b * C_ + h * HD) * HW_ + nblk * 64;
    int tid = threadIdx.x;

    int r = tid >> 6;        // 0..3
    int cidx = tid & 63;
#pragma unroll
    for (int rr = 0; rr < 16; rr++) {
        int dh = rr * 4 + r;
        tile[dh][cidx] = src[(size_t)dh * HW_ + cidx];
    }
    __syncthreads();

    float* dst = outv + ((((size_t)(t * B_ + b) * NH + h) * HW_) + nblk * 64) * HD;
    int dh = tid & 63, nl = tid >> 6;
#pragma unroll
    for (int nn = 0; nn < 16; nn++) {
        int n = nn * 4 + nl;
        dst[(size_t)n * HD + dh] = tile[dh][n];
    }
}

// ---------------------------------------------------------------------------
extern "C" void kernel_launch(void* const* d_in, const int* in_sizes, int n_in,
                              void* d_out, int out_size)
{
    const float* x       = (const float*)d_in[0];
    const float* Wq      = (const float*)d_in[1];
    const float* q_scale = (const float*)d_in[2];
    const float* q_bias  = (const float*)d_in[3];
    const float* Wk      = (const float*)d_in[4];
    const float* k_scale = (const float*)d_in[5];
    const float* k_bias  = (const float*)d_in[6];
    const float* Wv      = (const float*)d_in[7];
    const float* v_scale = (const float*)d_in[8];
    const float* v_bias  = (const float*)d_in[9];
    const float* Wp      = (const float*)d_in[10];
    const float* bp      = (const float*)d_in[11];
    const float* p_scale = (const float*)d_in[12];
    const float* p_bias  = (const float*)d_in[13];
    float* out = (float*)d_out;

    float *xs, *q, *k, *v, *x2, *attn;
    cudaGetSymbolAddress((void**)&xs,   g_xs);
    cudaGetSymbolAddress((void**)&q,    g_q);
    cudaGetSymbolAddress((void**)&k,    g_k);
    cudaGetSymbolAddress((void**)&v,    g_v);
    cudaGetSymbolAddress((void**)&x2,   g_x2);
    cudaGetSymbolAddress((void**)&attn, g_attn);

    const int EW_BLOCKS = SLICE / 256;
    dim3 gemm_grid(HW_ / 64, C_ / 64, T_ * B_);   // (4, 8, 128)

    // 1. shortcut LIF
    lif_in_kernel<<<EW_BLOCKS, 256>>>(x, xs);

    // 2. q/k/v conv + BN
    gemm_qkv_kernel<<<gemm_grid, 256>>>(Wq, xs, q, q_scale, q_bias);
    gemm_qkv_kernel<<<gemm_grid, 256>>>(Wk, xs, k, k_scale, k_bias);
    gemm_qkv_kernel<<<gemm_grid, 256>>>(Wv, xs, v, v_scale, v_bias);

    // 3. LIF on q/k/v (vth = 1.0), in place -> binary spikes
    lif_ip_kernel<<<EW_BLOCKS, 256>>>(q, 1.0f);
    lif_ip_kernel<<<EW_BLOCKS, 256>>>(k, 1.0f);
    lif_ip_kernel<<<EW_BLOCKS, 256>>>(v, 1.0f);

    // 4. attn = (1/16) k^T v per (chunk, b, h)
    attn_kernel<<<2 * B_ * NH, 256>>>(k, v, attn);

    // 5. x2 = attn^T @ q, LIF (vth=0.5) fused
    x2_lif_kernel<<<dim3(HW_ / 64, NH, B_), 256>>>(q, attn, x2);

    // 6. proj conv + BN + identity -> out[0 : TOTAL)
    gemm_proj_kernel<<<gemm_grid, 256>>>(Wp, x2, out, p_scale, p_bias, bp, x);

    // 7. v spikes -> out[TOTAL : 2*TOTAL) in [T,B,h,N,hd] layout
    vtrans_kernel<<<dim3(HW_ / 64, NH, T_ * B_), 256>>>(v, out + TOTAL);
}

// round 3
// speedup vs baseline: 2.4049x; 2.4049x over previous
#include <cuda_runtime.h>
#include <cuda_bf16.h>
#include <cstdint>

// Problem constants
#define T_    4
#define B_    32
#define C_    512
#define HW_   256
#define NH    8
#define HD    64
#define SLICE 4194304      // B*C*HW = one time slice
#define TOTAL 16777216     // T*B*C*HW
#define CN    131072       // C*HW per (t,b)

// ---------------------------------------------------------------------------
// helpers
// ---------------------------------------------------------------------------
__device__ __forceinline__ uint32_t smem_to_u32(const void* smem_ptr) {
    uint32_t addr;
    asm("{ .reg .u64 tmp; cvta.to.shared.u64 tmp, %1; cvt.u32.u64 %0, tmp; }"
        : "=r"(addr) : "l"(smem_ptr));
    return addr;
}

__device__ __forceinline__ void cp16(uint32_t dst, const void* src) {
    asm volatile("cp.async.ca.shared.global [%0], [%1], 16;" :: "r"(dst), "l"(src));
}

__device__ __forceinline__ void ldsm4(uint32_t* r, uint32_t addr) {
    asm volatile("ldmatrix.sync.aligned.m8n8.x4.shared.b16 {%0,%1,%2,%3}, [%4];"
                 : "=r"(r[0]), "=r"(r[1]), "=r"(r[2]), "=r"(r[3]) : "r"(addr));
}

__device__ __forceinline__ void mma16816(float* c, const uint32_t* a,
                                         uint32_t b0, uint32_t b1) {
    asm volatile(
        "mma.sync.aligned.m16n8k16.row.col.f32.bf16.bf16.f32 "
        "{%0,%1,%2,%3}, {%4,%5,%6,%7}, {%8,%9}, {%0,%1,%2,%3};"
        : "+f"(c[0]), "+f"(c[1]), "+f"(c[2]), "+f"(c[3])
        : "r"(a[0]), "r"(a[1]), "r"(a[2]), "r"(a[3]), "r"(b0), "r"(b1));
}

// ---------------------------------------------------------------------------
// Scratch (static device globals)
// ---------------------------------------------------------------------------
__device__ __nv_bfloat16 g_xsT[TOTAL];              // spikes of x, [tb][n][c] bf16 (K-major)
__device__ float         g_q [TOTAL];               // conv outputs -> spikes, fp32 [t,b,c,n]
__device__ float         g_k [TOTAL];
__device__ float         g_v [TOTAL];
__device__ __nv_bfloat16 g_x2T[TOTAL];              // x2 spikes, [tb][n][c] bf16
__device__ float         g_attn[2 * B_ * NH * HD * HD];
__device__ __nv_bfloat16 g_wsplit[3u * 2048u * 512u]; // [split][2048 rows: q,k,v,p][512]
__device__ float         g_scale[3 * C_];
__device__ float         g_bias [3 * C_];

// ---------------------------------------------------------------------------
// Prep: exact 3-way bf16 split of the 4 weight matrices
// ---------------------------------------------------------------------------
__global__ void wsplit_kernel(const float* __restrict__ Wq, const float* __restrict__ Wk,
                              const float* __restrict__ Wv, const float* __restrict__ Wp,
                              __nv_bfloat16* __restrict__ ws)
{
    int i = blockIdx.x * 256 + threadIdx.x;      // 0 .. 2048*512-1
    int r = i >> 9;
    int kk = i & 511;
    const float* W = (r < 512) ? Wq : (r < 1024) ? Wk : (r < 1536) ? Wv : Wp;
    float w = W[(size_t)(r & 511) * 512 + kk];
    __nv_bfloat16 hi = __float2bfloat16(w);
    float r1 = w - __bfloat162float(hi);
    __nv_bfloat16 mid = __float2bfloat16(r1);
    float r2 = r1 - __bfloat162float(mid);
    __nv_bfloat16 lo = __float2bfloat16(r2);
    ws[i]            = hi;
    ws[1048576u + i] = mid;
    ws[2097152u + i] = lo;
}

__global__ void sb_kernel(const float* __restrict__ qs, const float* __restrict__ qb,
                          const float* __restrict__ ks, const float* __restrict__ kb,
                          const float* __restrict__ vs, const float* __restrict__ vb,
                          float* __restrict__ gs, float* __restrict__ gb)
{
    int i = blockIdx.x * 256 + threadIdx.x;
    if (i >= 1536) return;
    if (i < 512)       { gs[i] = qs[i];        gb[i] = qb[i]; }
    else if (i < 1024) { gs[i] = ks[i - 512];  gb[i] = kb[i - 512]; }
    else               { gs[i] = vs[i - 1024]; gb[i] = vb[i - 1024]; }
}

// ---------------------------------------------------------------------------
// K1: shortcut LIF on x fused with transpose -> xsT bf16 [tb][n][c]
// grid (4 nblk, 8 cblk, 32 b), 256 threads; each thread owns 16 (c,n) cells
// ---------------------------------------------------------------------------
__global__ void lif_in_trans_kernel(const float* __restrict__ x,
                                    __nv_bfloat16* __restrict__ xsT)
{
    __shared__ __nv_bfloat16 tile[64][65];
    int nblk = blockIdx.x, cblk = blockIdx.y, b = blockIdx.z;
    int tid = threadIdx.x;

    float v[16];
#pragma unroll
    for (int p = 0; p < 16; p++) v[p] = 0.f;

#pragma unroll
    for (int t = 0; t < T_; t++) {
        if (t) __syncthreads();
#pragma unroll
        for (int p = 0; p < 16; p++) {
            int e = p * 256 + tid;
            int c_l = e >> 6, n_l = e & 63;
            float xv = x[(size_t)t * SLICE +
                         ((size_t)(b * C_ + cblk * 64 + c_l)) * HW_ + nblk * 64 + n_l];
            v[p] = v[p] + (xv - v[p]) * 0.5f;
            float s = (v[p] >= 1.0f) ? 1.0f : 0.0f;
            if (s != 0.f) v[p] = 0.f;
            tile[c_l][n_l] = __float2bfloat16(s);
        }
        __syncthreads();
        // write transposed: xsT[(t*32+b)][n][c]
        __nv_bfloat16* D = xsT + ((size_t)(t * B_ + b) * HW_) * C_;
#pragma unroll
        for (int p = 0; p < 16; p++) {
            int e = p * 256 + tid;
            int c_l = e & 63, n_l = e >> 6;
            D[(size_t)(nblk * 64 + n_l) * C_ + cblk * 64 + c_l] = tile[c_l][n_l];
        }
    }
}

// ---------------------------------------------------------------------------
// LIF in place on fp32 conv output
// ---------------------------------------------------------------------------
__global__ void lif_ip_kernel(float* __restrict__ y, float vth)
{
    int i = blockIdx.x * blockDim.x + threadIdx.x;
    if (i >= SLICE) return;
    float v = 0.f;
#pragma unroll
    for (int t = 0; t < T_; t++) {
        float xv = y[(size_t)t * SLICE + i];
        v = v + (xv - v) * 0.5f;
        float s = (v >= vth) ? 1.0f : 0.0f;
        y[(size_t)t * SLICE + i] = s;
        if (s != 0.f) v = 0.f;
    }
}

// ---------------------------------------------------------------------------
// HMMA GEMM: D[128,128] tile of (W3[M x 1536] * B[256 x 1536]^T) per tb
//   W3 = [Whi | Wmid | Wlo] along K'  (exact 3-split of fp32 weights)
//   B  = spike matrix stored [n][c] bf16 (xsT / x2T), reused for each split
// MODE 0: qkv epilogue  y = acc*scale + bias  -> q/k/v fp32
// MODE 1: proj epilogue out = (acc + cbias)*scale + bias + identity -> d_out
// grid (n_tiles=2, m_tiles, tb=128), 256 threads (2x4 warps of 64x32)
// ---------------------------------------------------------------------------
#define STAGE_BYTES 36864
#define A_BYTES     18432

template<int MODE>
__global__ void __launch_bounds__(256) gemm_hmma_kernel(
    const __nv_bfloat16* __restrict__ wsplit,     // [3][2048][512]
    const __nv_bfloat16* __restrict__ Bmat,       // [tb][256][512]
    float* __restrict__ oq, float* __restrict__ ok, float* __restrict__ ov,
    const float* __restrict__ scale, const float* __restrict__ bias,
    const float* __restrict__ cbias, const float* __restrict__ identity,
    float* __restrict__ outp, int wrow_base)
{
    extern __shared__ __align__(128) char smem[];
    uint32_t smem_u = smem_to_u32(smem);
    const int tid = threadIdx.x;
    const int wid = tid >> 5, lane = tid & 31;
    const int wm = wid >> 2, wn = wid & 3;         // 2 x 4 warp grid
    const int n0 = blockIdx.x * 128;
    const int m0 = blockIdx.y * 128;
    const int tb = blockIdx.z;
    const char* Bbase = (const char*)(Bmat + (size_t)tb * CN);

    float acc[4][4][4];
#pragma unroll
    for (int i = 0; i < 4; i++)
#pragma unroll
        for (int j = 0; j < 4; j++)
#pragma unroll
            for (int e = 0; e < 4; e++) acc[i][j][e] = 0.f;

    // ---- stage loader (cp.async, 16B granules) ----
    auto cp_stage = [&](int s) {
        int buf = s & 1;
        int kc0 = s << 6;
        int split = kc0 >> 9;
        int kA = kc0 & 511;
        const char* Ag = (const char*)wsplit
                       + ((size_t)split * 2048 + (size_t)(wrow_base + m0)) * 1024
                       + (size_t)kA * 2;
        const char* Bg = Bbase + (size_t)n0 * 1024 + (size_t)kA * 2;
        uint32_t sA = smem_u + buf * STAGE_BYTES;
        uint32_t sB = sA + A_BYTES;
#pragma unroll
        for (int p = 0; p < 4; p++) {
            int lin = p * 256 + tid;
            int r = lin >> 3, sg = lin & 7;
            cp16(sA + r * 144 + sg * 16, Ag + (size_t)r * 1024 + sg * 16);
            cp16(sB + r * 144 + sg * 16, Bg + (size_t)r * 1024 + sg * 16);
        }
        asm volatile("cp.async.commit_group;");
    };

    cp_stage(0);

    for (int s = 0; s < 24; s++) {
        if (s + 1 < 24) {
            cp_stage(s + 1);
            asm volatile("cp.async.wait_group 1;");
        } else {
            asm volatile("cp.async.wait_group 0;");
        }
        __syncthreads();

        uint32_t sA = smem_u + (s & 1) * STAGE_BYTES;
        uint32_t sB = sA + A_BYTES;

#pragma unroll
        for (int kk = 0; kk < 4; kk++) {
            uint32_t a[4][4];
#pragma unroll
            for (int i = 0; i < 4; i++) {
                uint32_t row = wm * 64 + i * 16 + (lane & 15);
                uint32_t col = kk * 16 + ((lane >> 4) << 3);
                ldsm4(a[i], sA + (row * 72 + col) * 2);
            }
            uint32_t bf[2][4];
#pragma unroll
            for (int j = 0; j < 2; j++) {
                uint32_t row = wn * 32 + j * 16 + (lane & 7) + ((lane >> 4) << 3);
                uint32_t col = kk * 16 + (((lane >> 3) & 1) << 3);
                ldsm4(bf[j], sB + (row * 72 + col) * 2);
            }
#pragma unroll
            for (int i = 0; i < 4; i++)
#pragma unroll
                for (int jj = 0; jj < 4; jj++) {
                    uint32_t b0 = bf[jj >> 1][(jj & 1) * 2 + 0];
                    uint32_t b1 = bf[jj >> 1][(jj & 1) * 2 + 1];
                    mma16816(acc[i][jj], a[i], b0, b1);
                }
        }
        __syncthreads();
    }

    // ---- epilogue ----
    int g = lane >> 2, tg = lane & 3;
#pragma unroll
    for (int i = 0; i < 4; i++) {
        int mloc = m0 + wm * 64 + i * 16 + g;
#pragma unroll
        for (int half = 0; half < 2; half++) {
            int row = mloc + half * 8;
            if (MODE == 0) {
                int tensor = row >> 9;
                int c = row & 511;
                float sc = scale[row], bi = bias[row];
                float* ybase = (tensor == 0) ? oq : (tensor == 1) ? ok : ov;
                float* dst = ybase + (size_t)tb * CN + (size_t)c * HW_;
#pragma unroll
                for (int jj = 0; jj < 4; jj++) {
                    int col = n0 + wn * 32 + jj * 8 + 2 * tg;
                    float2 v2;
                    v2.x = acc[i][jj][half * 2 + 0] * sc + bi;
                    v2.y = acc[i][jj][half * 2 + 1] * sc + bi;
                    *(float2*)&dst[col] = v2;
                }
            } else {
                int c = row;
                float sc = scale[c], bi = bias[c], cb = cbias[c];
                float* dst = outp + (size_t)tb * CN + (size_t)c * HW_;
                const float* idp = identity + (size_t)tb * CN + (size_t)c * HW_;
#pragma unroll
                for (int jj = 0; jj < 4; jj++) {
                    int col = n0 + wn * 32 + jj * 8 + 2 * tg;
                    float2 id2 = *(const float2*)&idp[col];
                    float2 v2;
                    v2.x = (acc[i][jj][half * 2 + 0] + cb) * sc + bi + id2.x;
                    v2.y = (acc[i][jj][half * 2 + 1] + cb) * sc + bi + id2.y;
                    *(float2*)&dst[col] = v2;
                }
            }
        }
    }
}

// ---------------------------------------------------------------------------
// K4: linear attention  attn[chunk,b,h,dh,de] = (1/16) * sum_{tc,n} k*v
// ---------------------------------------------------------------------------
__global__ void attn_kernel(const float* __restrict__ ksp,
                            const float* __restrict__ vsp,
                            float* __restrict__ attn)
{
    __shared__ float ks[64 * 65];
    __shared__ float vs[64 * 65];

    int cbh = blockIdx.x;
    int h = cbh & 7;
    int b = (cbh >> 3) & 31;
    int chunk = cbh >> 8;
    int tid = threadIdx.x;
    int tx = tid & 15, ty = tid >> 4;

    float acc[4][4] = {};

    for (int st = 0; st < 8; st++) {
        int t = chunk * 2 + (st >> 2);
        int n0 = (st & 3) * 64;
        const float* kp = ksp + (size_t)t * SLICE + ((size_t)b * C_ + h * HD) * HW_ + n0;
        const float* vp = vsp + (size_t)t * SLICE + ((size_t)b * C_ + h * HD) * HW_ + n0;
        __syncthreads();
#pragma unroll
        for (int p = 0; p < 4; p++) {
            int row = p * 16 + (tid >> 4);
            int col = (tid & 15) * 4;
            float4 kq = *(const float4*)&kp[(size_t)row * HW_ + col];
            ks[row * 65 + col + 0] = kq.x; ks[row * 65 + col + 1] = kq.y;
            ks[row * 65 + col + 2] = kq.z; ks[row * 65 + col + 3] = kq.w;
            float4 vq = *(const float4*)&vp[(size_t)row * HW_ + col];
            vs[row * 65 + col + 0] = vq.x; vs[row * 65 + col + 1] = vq.y;
            vs[row * 65 + col + 2] = vq.z; vs[row * 65 + col + 3] = vq.w;
        }
        __syncthreads();
#pragma unroll 16
        for (int ss = 0; ss < 64; ss++) {
            float a[4], bv[4];
#pragma unroll
            for (int i = 0; i < 4; i++) a[i] = ks[(ty * 4 + i) * 65 + ss];
#pragma unroll
            for (int j = 0; j < 4; j++) bv[j] = vs[(tx * 4 + j) * 65 + ss];
#pragma unroll
            for (int i = 0; i < 4; i++)
#pragma unroll
                for (int j = 0; j < 4; j++) acc[i][j] += a[i] * bv[j];
        }
    }

    float* ap = attn + ((((size_t)chunk * B_ + b) * NH + h) * HD) * HD;
#pragma unroll
    for (int i = 0; i < 4; i++)
#pragma unroll
        for (int j = 0; j < 4; j++)
            ap[(ty * 4 + i) * HD + tx * 4 + j] = acc[i][j] * 0.0625f;
}

// ---------------------------------------------------------------------------
// K5: x2 = attn^T @ q with LIF (vth=0.5), writes TRANSPOSED bf16 spikes [tb][n][c]
// ---------------------------------------------------------------------------
__global__ void x2_lif_kernel(const float* __restrict__ qsp,
                              const float* __restrict__ attn,
                              __nv_bfloat16* __restrict__ x2T)
{
    __shared__ float a_s[64 * 64];
    __shared__ float q_s[64 * 64];

    int nblk = blockIdx.x, h = blockIdx.y, b = blockIdx.z;
    int n0 = nblk * 64;
    int tid = threadIdx.x;
    int tx = tid & 15, ty = tid >> 4;

    float acc[T_][4][4];
#pragma unroll
    for (int t = 0; t < T_; t++)
#pragma unroll
        for (int i = 0; i < 4; i++)
#pragma unroll
            for (int j = 0; j < 4; j++) acc[t][i][j] = 0.f;

#pragma unroll
    for (int t = 0; t < T_; t++) {
        int chunk = t >> 1;
        __syncthreads();
        if ((t & 1) == 0) {
            const float* ap = attn + ((((size_t)chunk * B_ + b) * NH + h) * HD) * HD;
#pragma unroll
            for (int p = 0; p < 4; p++) {
                int idx = p * 1024 + tid * 4;
                *(float4*)&a_s[idx] = *(const float4*)&ap[idx];
            }
        }
        const float* qp = qsp + (size_t)t * SLICE + ((size_t)b * C_ + h * HD) * HW_ + n0;
#pragma unroll
        for (int p = 0; p < 4; p++) {
            int row = p * 16 + (tid >> 4);
            int col = (tid & 15) * 4;
            *(float4*)&q_s[row * 64 + col] = *(const float4*)&qp[(size_t)row * HW_ + col];
        }
        __syncthreads();
#pragma unroll 16
        for (int kk = 0; kk < 64; kk++) {
            float a[4], bv[4];
#pragma unroll
            for (int i = 0; i < 4; i++) a[i] = a_s[kk * 64 + ty * 4 + i];
#pragma unroll
            for (int j = 0; j < 4; j++) bv[j] = q_s[kk * 64 + tx * 4 + j];
#pragma unroll
            for (int i = 0; i < 4; i++)
#pragma unroll
                for (int j = 0; j < 4; j++) acc[t][i][j] += a[i] * bv[j];
        }
    }

    // LIF over t (vth = 0.5) in registers
#pragma unroll
    for (int i = 0; i < 4; i++)
#pragma unroll
        for (int j = 0; j < 4; j++) {
            float v = 0.f;
#pragma unroll
            for (int t = 0; t < T_; t++) {
                float xv = acc[t][i][j];
                v = v + (xv - v) * 0.5f;
                float s = (v >= 0.5f) ? 1.0f : 0.0f;
                acc[t][i][j] = s;
                if (s != 0.f) v = 0.f;
            }
        }

    // write bf16 transposed: x2T[(t*B+b)*256 + n][c]
    int c0 = h * HD + ty * 4;
#pragma unroll
    for (int t = 0; t < T_; t++) {
        __nv_bfloat16* base = x2T + ((size_t)(t * B_ + b) * HW_) * C_;
#pragma unroll
        for (int j = 0; j < 4; j++) {
            int n = n0 + tx * 4 + j;
            __nv_bfloat16 tmp[4];
            tmp[0] = __float2bfloat16(acc[t][0][j]);
            tmp[1] = __float2bfloat16(acc[t][1][j]);
            tmp[2] = __float2bfloat16(acc[t][2][j]);
            tmp[3] = __float2bfloat16(acc[t][3][j]);
            *(uint2*)(base + (size_t)n * C_ + c0) = *(uint2*)tmp;
        }
    }
}

// ---------------------------------------------------------------------------
// K7: v spikes transpose to output layout [T,B,h,N,hd]
// ---------------------------------------------------------------------------
__global__ void vtrans_kernel(const float* __restrict__ vsp, float* __restrict__ outv)
{
    __shared__ float tile[64][65];
    int nblk = blockIdx.x, h = blockIdx.y, tb = blockIdx.z;
    int t = tb >> 5, b = tb & 31;
    const float* src = vsp + (size_t)t * SLICE + ((size_t)b * C_ + h * HD) * HW_ + nblk * 64;
    int tid = threadIdx.x;

    int r = tid >> 6;
    int cidx = tid & 63;
#pragma unroll
    for (int rr = 0; rr < 16; rr++) {
        int dh = rr * 4 + r;
        tile[dh][cidx] = src[(size_t)dh * HW_ + cidx];
    }
    __syncthreads();

    float* dst = outv + ((((size_t)(t * B_ + b) * NH + h) * HW_) + nblk * 64) * HD;
    int dh = tid & 63, nl = tid >> 6;
#pragma unroll
    for (int nn = 0; nn < 16; nn++) {
        int n = nn * 4 + nl;
        dst[(size_t)n * HD + dh] = tile[dh][n];
    }
}

// ---------------------------------------------------------------------------
extern "C" void kernel_launch(void* const* d_in, const int* in_sizes, int n_in,
                              void* d_out, int out_size)
{
    const float* x       = (const float*)d_in[0];
    const float* Wq      = (const float*)d_in[1];
    const float* q_scale = (const float*)d_in[2];
    const float* q_bias  = (const float*)d_in[3];
    const float* Wk      = (const float*)d_in[4];
    const float* k_scale = (const float*)d_in[5];
    const float* k_bias  = (const float*)d_in[6];
    const float* Wv      = (const float*)d_in[7];
    const float* v_scale = (const float*)d_in[8];
    const float* v_bias  = (const float*)d_in[9];
    const float* Wp      = (const float*)d_in[10];
    const float* bp      = (const float*)d_in[11];
    const float* p_scale = (const float*)d_in[12];
    const float* p_bias  = (const float*)d_in[13];
    float* out = (float*)d_out;

    __nv_bfloat16 *xsT, *x2T, *wsplit;
    float *q, *k, *v, *attn, *gscale, *gbias;
    cudaGetSymbolAddress((void**)&xsT,    g_xsT);
    cudaGetSymbolAddress((void**)&q,      g_q);
    cudaGetSymbolAddress((void**)&k,      g_k);
    cudaGetSymbolAddress((void**)&v,      g_v);
    cudaGetSymbolAddress((void**)&x2T,    g_x2T);
    cudaGetSymbolAddress((void**)&attn,   g_attn);
    cudaGetSymbolAddress((void**)&wsplit, g_wsplit);
    cudaGetSymbolAddress((void**)&gscale, g_scale);
    cudaGetSymbolAddress((void**)&gbias,  g_bias);

    const int SMEM_BYTES = 2 * STAGE_BYTES;   // 73728
    cudaFuncSetAttribute(gemm_hmma_kernel<0>, cudaFuncAttributeMaxDynamicSharedMemorySize, SMEM_BYTES);
    cudaFuncSetAttribute(gemm_hmma_kernel<1>, cudaFuncAttributeMaxDynamicSharedMemorySize, SMEM_BYTES);

    const int EW_BLOCKS = SLICE / 256;

    // 0. weight splits + scale/bias concat
    wsplit_kernel<<<4096, 256>>>(Wq, Wk, Wv, Wp, wsplit);
    sb_kernel<<<6, 256>>>(q_scale, q_bias, k_scale, k_bias, v_scale, v_bias, gscale, gbias);

    // 1. shortcut LIF fused with transpose -> bf16 spikes [tb][n][c]
    lif_in_trans_kernel<<<dim3(4, 8, 32), 256>>>(x, xsT);

    // 2. q/k/v conv + BN via HMMA (exact 3-split bf16, augmented K=1536)
    gemm_hmma_kernel<0><<<dim3(2, 12, 128), 256, SMEM_BYTES>>>(
        wsplit, xsT, q, k, v, gscale, gbias, nullptr, nullptr, nullptr, 0);

    // 3. LIF on q/k/v (vth = 1.0), in place -> binary fp32 spikes
    lif_ip_kernel<<<EW_BLOCKS, 256>>>(q, 1.0f);
    lif_ip_kernel<<<EW_BLOCKS, 256>>>(k, 1.0f);
    lif_ip_kernel<<<EW_BLOCKS, 256>>>(v, 1.0f);

    // 4. attn = (1/16) k^T v per (chunk, b, h)
    attn_kernel<<<2 * B_ * NH, 256>>>(k, v, attn);

    // 5. x2 = attn^T @ q + LIF(0.5), writes transposed bf16 spikes
    x2_lif_kernel<<<dim3(HW_ / 64, NH, B_), 256>>>(q, attn, x2T);

    // 6. proj conv + BN + identity via HMMA -> out[0 : TOTAL)
    gemm_hmma_kernel<1><<<dim3(2, 4, 128), 256, SMEM_BYTES>>>(
        wsplit, x2T, nullptr, nullptr, nullptr, p_scale, p_bias, bp, x, out, 1536);

    // 7. v spikes -> out[TOTAL : 2*TOTAL) in [T,B,h,N,hd] layout
    vtrans_kernel<<<dim3(HW_ / 64, NH, T_ * B_), 256>>>(v, out + TOTAL);
}

// round 4
// speedup vs baseline: 3.8816x; 1.6140x over previous
#include <cuda_runtime.h>
#include <cuda_fp16.h>
#include <cstdint>

// Problem constants
#define T_    4
#define B_    32
#define C_    512
#define HW_   256
#define NH    8
#define HD    64
#define SLICE 4194304      // B*C*HW = one time slice
#define TOTAL 16777216     // T*B*C*HW
#define CN    131072       // C*HW per (t,b)

// ---------------------------------------------------------------------------
// helpers
// ---------------------------------------------------------------------------
__device__ __forceinline__ uint32_t smem_to_u32(const void* smem_ptr) {
    uint32_t addr;
    asm("{ .reg .u64 tmp; cvta.to.shared.u64 tmp, %1; cvt.u32.u64 %0, tmp; }"
        : "=r"(addr) : "l"(smem_ptr));
    return addr;
}

__device__ __forceinline__ void cp16(uint32_t dst, const void* src) {
    asm volatile("cp.async.ca.shared.global [%0], [%1], 16;" :: "r"(dst), "l"(src));
}

__device__ __forceinline__ void ldsm4(uint32_t* r, uint32_t addr) {
    asm volatile("ldmatrix.sync.aligned.m8n8.x4.shared.b16 {%0,%1,%2,%3}, [%4];"
                 : "=r"(r[0]), "=r"(r[1]), "=r"(r[2]), "=r"(r[3]) : "r"(addr));
}

__device__ __forceinline__ void mma16816h(float* c, const uint32_t* a,
                                          uint32_t b0, uint32_t b1) {
    asm volatile(
        "mma.sync.aligned.m16n8k16.row.col.f32.f16.f16.f32 "
        "{%0,%1,%2,%3}, {%4,%5,%6,%7}, {%8,%9}, {%0,%1,%2,%3};"
        : "+f"(c[0]), "+f"(c[1]), "+f"(c[2]), "+f"(c[3])
        : "r"(a[0]), "r"(a[1]), "r"(a[2]), "r"(a[3]), "r"(b0), "r"(b1));
}

// ---------------------------------------------------------------------------
// Scratch (static device globals)
// ---------------------------------------------------------------------------
__device__ __half g_xsT[TOTAL];              // spikes of x, [tb][n][c] fp16 (K-major)
__device__ float  g_q [TOTAL];               // conv outputs fp32 [t,b,c,n]
__device__ float  g_k [TOTAL];
__device__ float  g_v [TOTAL];
__device__ __half g_qT[TOTAL];               // q spikes, [tb][n][c] fp16
__device__ __half g_ks[TOTAL];               // k spikes, [t,b,c,n] fp16
__device__ __half g_vs[TOTAL];               // v spikes, [t,b,c,n] fp16
__device__ __half g_x2T[TOTAL];              // x2 spikes, [tb][n][c] fp16
__device__ __half g_attnT[2 * B_ * NH * HD * HD];   // [chunk,b,h][de][dh]
__device__ __half g_wsplit[2u * 2048u * 512u];      // [split: 0=mid',1=hi][2048][512]
__device__ float  g_scale[3 * C_];
__device__ float  g_bias [3 * C_];

// ---------------------------------------------------------------------------
// Prep: exact 2-way fp16 split of the 4 weight matrices
//   w = hi + mid' * 2^-12   (mid' = fp16(r1*4096) stays in normal fp16 range)
// ---------------------------------------------------------------------------
__global__ void wsplit_kernel(const float* __restrict__ Wq, const float* __restrict__ Wk,
                              const float* __restrict__ Wv, const float* __restrict__ Wp,
                              __half* __restrict__ ws)
{
    int i = blockIdx.x * 256 + threadIdx.x;      // 0 .. 2048*512-1
    int r = i >> 9;
    int kk = i & 511;
    const float* W = (r < 512) ? Wq : (r < 1024) ? Wk : (r < 1536) ? Wv : Wp;
    float w = W[(size_t)(r & 511) * 512 + kk];
    __half hi = __float2half_rn(w);
    float r1 = w - __half2float(hi);
    __half mid = __float2half_rn(r1 * 4096.0f);
    ws[i]            = mid;     // split 0 = scaled mid (accumulated first)
    ws[1048576u + i] = hi;      // split 1 = hi
}

__global__ void sb_kernel(const float* __restrict__ qs, const float* __restrict__ qb,
                          const float* __restrict__ ks, const float* __restrict__ kb,
                          const float* __restrict__ vs, const float* __restrict__ vb,
                          float* __restrict__ gs, float* __restrict__ gb)
{
    int i = blockIdx.x * 256 + threadIdx.x;
    if (i >= 1536) return;
    if (i < 512)       { gs[i] = qs[i];        gb[i] = qb[i]; }
    else if (i < 1024) { gs[i] = ks[i - 512];  gb[i] = kb[i - 512]; }
    else               { gs[i] = vs[i - 1024]; gb[i] = vb[i - 1024]; }
}

// ---------------------------------------------------------------------------
// K1: shortcut LIF on x fused with transpose -> xsT fp16 [tb][n][c]
// ---------------------------------------------------------------------------
__global__ void lif_in_trans_kernel(const float* __restrict__ x,
                                    __half* __restrict__ xsT)
{
    __shared__ __half tile[64][65];
    int nblk = blockIdx.x, cblk = blockIdx.y, b = blockIdx.z;
    int tid = threadIdx.x;

    float v[16];
#pragma unroll
    for (int p = 0; p < 16; p++) v[p] = 0.f;

#pragma unroll
    for (int t = 0; t < T_; t++) {
        if (t) __syncthreads();
#pragma unroll
        for (int p = 0; p < 16; p++) {
            int c_l = p * 4 + (tid >> 6), n_l = tid & 63;
            float xv = x[(size_t)t * SLICE +
                         ((size_t)(b * C_ + cblk * 64 + c_l)) * HW_ + nblk * 64 + n_l];
            v[p] = v[p] + (xv - v[p]) * 0.5f;
            float s = (v[p] >= 1.0f) ? 1.0f : 0.0f;
            if (s != 0.f) v[p] = 0.f;
            tile[c_l][n_l] = __float2half(s);
        }
        __syncthreads();
        __half* D = xsT + ((size_t)(t * B_ + b) * HW_) * C_;
#pragma unroll
        for (int p = 0; p < 16; p++) {
            int c_l = tid & 63, n_l = p * 4 + (tid >> 6);
            D[(size_t)(nblk * 64 + n_l) * C_ + cblk * 64 + c_l] = tile[c_l][n_l];
        }
    }
}

// ---------------------------------------------------------------------------
// Fused LIF on q/k/v conv outputs (vth=1):
//   qT  fp16 [tb][n][c]  (transposed, for x2 HMMA B-operand)
//   ks  fp16 [t,b,c,n]   (for attn HMMA)
//   vs  fp16 [t,b,c,n]   (for attn HMMA)
//   vout fp32 [t,b,h,n,dh]  (second output tensor, transposed tile)
// grid (4 nblk, 8 cblk(=h), 32 b), 256 threads
// ---------------------------------------------------------------------------
__global__ void lif_qkv_kernel(const float* __restrict__ q, const float* __restrict__ k,
                               const float* __restrict__ v,
                               __half* __restrict__ qT, __half* __restrict__ ks,
                               __half* __restrict__ vs, float* __restrict__ vout)
{
    __shared__ float tile[64][65];
    int nblk = blockIdx.x, cblk = blockIdx.y, b = blockIdx.z;
    int tid = threadIdx.x;
    int rsub = tid >> 6;         // 0..3
    int lan  = tid & 63;

    float mq[16], mk[16], mv[16];
#pragma unroll
    for (int p = 0; p < 16; p++) { mq[p] = 0.f; mk[p] = 0.f; mv[p] = 0.f; }

#pragma unroll
    for (int t = 0; t < T_; t++) {
        size_t base = (size_t)t * SLICE + ((size_t)(b * C_ + cblk * 64)) * HW_ + nblk * 64;

        // ---- q: LIF -> smem tile -> transposed fp16 write ----
#pragma unroll
        for (int p = 0; p < 16; p++) {
            int c_l = p * 4 + rsub;
            float xv = q[base + (size_t)c_l * HW_ + lan];
            mq[p] = mq[p] + (xv - mq[p]) * 0.5f;
            float s = (mq[p] >= 1.0f) ? 1.0f : 0.0f;
            if (s != 0.f) mq[p] = 0.f;
            tile[c_l][lan] = s;
        }
        __syncthreads();
        {
            __half* qrow = qT + ((size_t)(t * B_ + b) * HW_ + nblk * 64) * C_ + cblk * 64;
#pragma unroll
            for (int p = 0; p < 16; p++) {
                int n_l = p * 4 + rsub;
                qrow[(size_t)n_l * C_ + lan] = __float2half(tile[lan][n_l]);
            }
        }
        __syncthreads();

        // ---- k: LIF -> direct fp16 write [c][n] ----
#pragma unroll
        for (int p = 0; p < 16; p++) {
            int c_l = p * 4 + rsub;
            float xv = k[base + (size_t)c_l * HW_ + lan];
            mk[p] = mk[p] + (xv - mk[p]) * 0.5f;
            float s = (mk[p] >= 1.0f) ? 1.0f : 0.0f;
            if (s != 0.f) mk[p] = 0.f;
            ks[base + (size_t)c_l * HW_ + lan] = __float2half(s);
        }

        // ---- v: LIF -> fp16 [c][n] + fp32 transposed output ----
#pragma unroll
        for (int p = 0; p < 16; p++) {
            int c_l = p * 4 + rsub;
            float xv = v[base + (size_t)c_l * HW_ + lan];
            mv[p] = mv[p] + (xv - mv[p]) * 0.5f;
            float s = (mv[p] >= 1.0f) ? 1.0f : 0.0f;
            if (s != 0.f) mv[p] = 0.f;
            vs[base + (size_t)c_l * HW_ + lan] = __float2half(s);
            tile[c_l][lan] = s;
        }
        __syncthreads();
        {
            float* vrow = vout + (((size_t)(t * B_ + b) * NH + cblk) * HW_ + nblk * 64) * HD;
#pragma unroll
            for (int p = 0; p < 16; p++) {
                int n_l = p * 4 + rsub;
                vrow[(size_t)n_l * HD + lan] = tile[lan][n_l];
            }
        }
        __syncthreads();
    }
}

// ---------------------------------------------------------------------------
// HMMA GEMM: D[128,128] tile of (W2[M x 1024] * B[256 x 1024]^T) per tb
//   stages 0..7: mid' split, then acc *= 2^-12, stages 8..15: hi split (exact)
// MODE 0: qkv epilogue;  MODE 1: proj epilogue with identity add
// grid (n_tiles=2, m_tiles, tb=128), 256 threads (2x4 warps of 64x32)
// ---------------------------------------------------------------------------
#define STAGE_BYTES 36864
#define A_BYTES     18432

template<int MODE>
__global__ void __launch_bounds__(256) gemm_hmma_kernel(
    const __half* __restrict__ wsplit,            // [2][2048][512]
    const __half* __restrict__ Bmat,              // [tb][256][512]
    float* __restrict__ oq, float* __restrict__ ok, float* __restrict__ ov,
    const float* __restrict__ scale, const float* __restrict__ bias,
    const float* __restrict__ cbias, const float* __restrict__ identity,
    float* __restrict__ outp, int wrow_base)
{
    extern __shared__ __align__(128) char smem[];
    uint32_t smem_u = smem_to_u32(smem);
    const int tid = threadIdx.x;
    const int wid = tid >> 5, lane = tid & 31;
    const int wm = wid >> 2, wn = wid & 3;         // 2 x 4 warp grid
    const int n0 = blockIdx.x * 128;
    const int m0 = blockIdx.y * 128;
    const int tb = blockIdx.z;
    const char* Bbase = (const char*)(Bmat + (size_t)tb * CN);

    float acc[4][4][4];
#pragma unroll
    for (int i = 0; i < 4; i++)
#pragma unroll
        for (int j = 0; j < 4; j++)
#pragma unroll
            for (int e = 0; e < 4; e++) acc[i][j][e] = 0.f;

    auto cp_stage = [&](int s) {
        int buf = s & 1;
        int split = s >> 3;               // 0 = mid', 1 = hi
        int kA = (s & 7) << 6;
        const char* Ag = (const char*)wsplit
                       + ((size_t)split * 2048 + (size_t)(wrow_base + m0)) * 1024
                       + (size_t)kA * 2;
        const char* Bg = Bbase + (size_t)n0 * 1024 + (size_t)kA * 2;
        uint32_t sA = smem_u + buf * STAGE_BYTES;
        uint32_t sB = sA + A_BYTES;
#pragma unroll
        for (int p = 0; p < 4; p++) {
            int lin = p * 256 + tid;
            int r = lin >> 3, sg = lin & 7;
            cp16(sA + r * 144 + sg * 16, Ag + (size_t)r * 1024 + sg * 16);
            cp16(sB + r * 144 + sg * 16, Bg + (size_t)r * 1024 + sg * 16);
        }
        asm volatile("cp.async.commit_group;");
    };

    cp_stage(0);

    for (int s = 0; s < 16; s++) {
        if (s + 1 < 16) {
            cp_stage(s + 1);
            asm volatile("cp.async.wait_group 1;");
        } else {
            asm volatile("cp.async.wait_group 0;");
        }
        __syncthreads();

        uint32_t sA = smem_u + (s & 1) * STAGE_BYTES;
        uint32_t sB = sA + A_BYTES;

#pragma unroll
        for (int kk = 0; kk < 4; kk++) {
            uint32_t a[4][4];
#pragma unroll
            for (int i = 0; i < 4; i++) {
                uint32_t row = wm * 64 + i * 16 + (lane & 15);
                uint32_t col = kk * 16 + ((lane >> 4) << 3);
                ldsm4(a[i], sA + (row * 72 + col) * 2);
            }
            uint32_t bf[2][4];
#pragma unroll
            for (int j = 0; j < 2; j++) {
                uint32_t row = wn * 32 + j * 16 + (lane & 7) + ((lane >> 4) << 3);
                uint32_t col = kk * 16 + (((lane >> 3) & 1) << 3);
                ldsm4(bf[j], sB + (row * 72 + col) * 2);
            }
#pragma unroll
            for (int i = 0; i < 4; i++)
#pragma unroll
                for (int jj = 0; jj < 4; jj++) {
                    uint32_t b0 = bf[jj >> 1][(jj & 1) * 2 + 0];
                    uint32_t b1 = bf[jj >> 1][(jj & 1) * 2 + 1];
                    mma16816h(acc[i][jj], a[i], b0, b1);
                }
        }
        if (s == 7) {
            // fold the scaled mid split: acc *= 2^-12 (exact)
#pragma unroll
            for (int i = 0; i < 4; i++)
#pragma unroll
                for (int j = 0; j < 4; j++)
#pragma unroll
                    for (int e = 0; e < 4; e++) acc[i][j][e] *= 0.000244140625f;
        }
        __syncthreads();
    }

    // ---- epilogue ----
    int g = lane >> 2, tg = lane & 3;
#pragma unroll
    for (int i = 0; i < 4; i++) {
        int mloc = m0 + wm * 64 + i * 16 + g;
#pragma unroll
        for (int half = 0; half < 2; half++) {
            int row = mloc + half * 8;
            if (MODE == 0) {
                int tensor = row >> 9;
                int c = row & 511;
                float sc = scale[row], bi = bias[row];
                float* ybase = (tensor == 0) ? oq : (tensor == 1) ? ok : ov;
                float* dst = ybase + (size_t)tb * CN + (size_t)c * HW_;
#pragma unroll
                for (int jj = 0; jj < 4; jj++) {
                    int col = n0 + wn * 32 + jj * 8 + 2 * tg;
                    float2 v2;
                    v2.x = acc[i][jj][half * 2 + 0] * sc + bi;
                    v2.y = acc[i][jj][half * 2 + 1] * sc + bi;
                    *(float2*)&dst[col] = v2;
                }
            } else {
                int c = row;
                float sc = scale[c], bi = bias[c], cb = cbias[c];
                float* dst = outp + (size_t)tb * CN + (size_t)c * HW_;
                const float* idp = identity + (size_t)tb * CN + (size_t)c * HW_;
#pragma unroll
                for (int jj = 0; jj < 4; jj++) {
                    int col = n0 + wn * 32 + jj * 8 + 2 * tg;
                    float2 id2 = *(const float2*)&idp[col];
                    float2 v2;
                    v2.x = (acc[i][jj][half * 2 + 0] + cb) * sc + bi + id2.x;
                    v2.y = (acc[i][jj][half * 2 + 1] + cb) * sc + bi + id2.y;
                    *(float2*)&dst[col] = v2;
                }
            }
        }
    }
}

// ---------------------------------------------------------------------------
// attn HMMA: attnT[chunk,b,h][de][dh] = (1/16) * sum_{t in chunk, s} v[de,s]*k[dh,s]
// A = v spikes [de][s] fp16, B = k spikes [dh][s] fp16, acc fp32 (exact counts)
// grid 512 = chunk*256 + b*8 + h; 128 threads (4 warps, m=de split)
// ---------------------------------------------------------------------------
__global__ void __launch_bounds__(128) attn_hmma_kernel(
    const __half* __restrict__ ksp, const __half* __restrict__ vsp,
    __half* __restrict__ attnT)
{
    __shared__ __half sv[64][72];
    __shared__ __half sk[64][72];
    uint32_t sv_u = smem_to_u32(&sv[0][0]);
    uint32_t sk_u = smem_to_u32(&sk[0][0]);

    int cbh = blockIdx.x;
    int h = cbh & 7, b = (cbh >> 3) & 31, chunk = cbh >> 8;
    int tid = threadIdx.x;
    int wid = tid >> 5, lane = tid & 31;

    float acc[8][4];
#pragma unroll
    for (int j = 0; j < 8; j++)
#pragma unroll
        for (int e = 0; e < 4; e++) acc[j][e] = 0.f;

    for (int st = 0; st < 8; st++) {
        int t = chunk * 2 + (st >> 2);
        int n0 = (st & 3) * 64;
        size_t base = (size_t)t * SLICE + ((size_t)(b * C_ + h * HD)) * HW_ + n0;
#pragma unroll
        for (int l = 0; l < 4; l++) {
            int lin = l * 128 + tid;
            int r = lin >> 3, sg = lin & 7;
            *(uint4*)((char*)sv + r * 144 + sg * 16) =
                *(const uint4*)(vsp + base + (size_t)r * HW_ + sg * 8);
            *(uint4*)((char*)sk + r * 144 + sg * 16) =
                *(const uint4*)(ksp + base + (size_t)r * HW_ + sg * 8);
        }
        __syncthreads();

#pragma unroll
        for (int kk = 0; kk < 4; kk++) {
            uint32_t a[4];
            {
                uint32_t row = wid * 16 + (lane & 15);
                uint32_t col = kk * 16 + ((lane >> 4) << 3);
                ldsm4(a, sv_u + (row * 72 + col) * 2);
            }
            uint32_t bf[4][4];
#pragma unroll
            for (int j2 = 0; j2 < 4; j2++) {
                uint32_t row = j2 * 16 + (lane & 7) + ((lane >> 4) << 3);
                uint32_t col = kk * 16 + (((lane >> 3) & 1) << 3);
                ldsm4(bf[j2], sk_u + (row * 72 + col) * 2);
            }
#pragma unroll
            for (int j = 0; j < 8; j++)
                mma16816h(acc[j], a, bf[j >> 1][(j & 1) * 2], bf[j >> 1][(j & 1) * 2 + 1]);
        }
        __syncthreads();
    }

    // write attnT fp16 (values = count/16, exact)
    __half* ap = attnT + ((size_t)((chunk * B_ + b) * NH + h)) * (HD * HD);
    int g = lane >> 2, tg = lane & 3;
#pragma unroll
    for (int j = 0; j < 8; j++)
#pragma unroll
        for (int e = 0; e < 2; e++) {
            int row = wid * 16 + g + e * 8;       // de
            int col = j * 8 + tg * 2;             // dh
            __half2 h2 = __floats2half2_rn(acc[j][e * 2] * 0.0625f,
                                           acc[j][e * 2 + 1] * 0.0625f);
            *(__half2*)(ap + (size_t)row * HD + col) = h2;
        }
}

// ---------------------------------------------------------------------------
// x2 HMMA + LIF(0.5): out[de][n] = sum_dh attnT[de][dh] * qT[n][h*64+dh]
// per t; LIF across t in registers; writes x2T fp16 [tb][n][c] (scattered b16)
// grid (2 nhalf, 8 h, 32 b), 256 threads (8 warps: 4(de) x 2(n64))
// ---------------------------------------------------------------------------
__global__ void __launch_bounds__(256) x2_hmma_kernel(
    const __half* __restrict__ qT, const __half* __restrict__ attnT,
    __half* __restrict__ x2T)
{
    __shared__ __half sq[128][72];
    __shared__ __half sa[64][72];
    uint32_t sq_u = smem_to_u32(&sq[0][0]);
    uint32_t sa_u = smem_to_u32(&sa[0][0]);

    int nhalf = blockIdx.x, h = blockIdx.y, b = blockIdx.z;
    int tid = threadIdx.x;
    int wid = tid >> 5, lane = tid & 31;
    int wm = wid >> 1, wn = wid & 1;

    float mem[8][4];
#pragma unroll
    for (int j = 0; j < 8; j++)
#pragma unroll
        for (int e = 0; e < 4; e++) mem[j][e] = 0.f;

#pragma unroll
    for (int t = 0; t < T_; t++) {
        // load attnT slice for this chunk (t=0 and t=2)
        if ((t & 1) == 0) {
            int chunk = t >> 1;
            const __half* ap = attnT + ((size_t)((chunk * B_ + b) * NH + h)) * (HD * HD);
#pragma unroll
            for (int l = 0; l < 2; l++) {
                int lin = l * 256 + tid;
                int r = lin >> 3, sg = lin & 7;
                *(uint4*)((char*)sa + r * 144 + sg * 16) =
                    *(const uint4*)(ap + (size_t)r * HD + sg * 8);
            }
        }
        // load qT slice [128 n][64 c]
        {
            const __half* qp = qT + ((size_t)(t * B_ + b) * HW_ + nhalf * 128) * C_ + h * HD;
#pragma unroll
            for (int l = 0; l < 4; l++) {
                int lin = l * 256 + tid;
                int r = lin >> 3, sg = lin & 7;
                *(uint4*)((char*)sq + r * 144 + sg * 16) =
                    *(const uint4*)(qp + (size_t)r * C_ + sg * 8);
            }
        }
        __syncthreads();

        float acc[8][4];
#pragma unroll
        for (int j = 0; j < 8; j++)
#pragma unroll
            for (int e = 0; e < 4; e++) acc[j][e] = 0.f;

#pragma unroll
        for (int kk = 0; kk < 4; kk++) {
            uint32_t a[4];
            {
                uint32_t row = wm * 16 + (lane & 15);
                uint32_t col = kk * 16 + ((lane >> 4) << 3);
                ldsm4(a, sa_u + (row * 72 + col) * 2);
            }
            uint32_t bf[4][4];
#pragma unroll
            for (int j2 = 0; j2 < 4; j2++) {
                uint32_t row = wn * 64 + j2 * 16 + (lane & 7) + ((lane >> 4) << 3);
                uint32_t col = kk * 16 + (((lane >> 3) & 1) << 3);
                ldsm4(bf[j2], sq_u + (row * 72 + col) * 2);
            }
#pragma unroll
            for (int j = 0; j < 8; j++)
                mma16816h(acc[j], a, bf[j >> 1][(j & 1) * 2], bf[j >> 1][(j & 1) * 2 + 1]);
        }

        // LIF (vth = 0.5) + scattered fp16 store to x2T[n][c]
        int g = lane >> 2, tg = lane & 3;
        size_t obase = ((size_t)(t * B_ + b) * HW_ + nhalf * 128) * C_ + h * HD;
#pragma unroll
        for (int j = 0; j < 8; j++)
#pragma unroll
            for (int e = 0; e < 4; e++) {
                float xv = acc[j][e];
                mem[j][e] = mem[j][e] + (xv - mem[j][e]) * 0.5f;
                float s = (mem[j][e] >= 0.5f) ? 1.0f : 0.0f;
                if (s != 0.f) mem[j][e] = 0.f;
                int n = wn * 64 + j * 8 + tg * 2 + (e & 1);
                int de = wm * 16 + g + ((e >> 1) << 3);
                x2T[obase + (size_t)n * C_ + de] = __float2half(s);
            }
        __syncthreads();
    }
}

// ---------------------------------------------------------------------------
extern "C" void kernel_launch(void* const* d_in, const int* in_sizes, int n_in,
                              void* d_out, int out_size)
{
    const float* x       = (const float*)d_in[0];
    const float* Wq      = (const float*)d_in[1];
    const float* q_scale = (const float*)d_in[2];
    const float* q_bias  = (const float*)d_in[3];
    const float* Wk      = (const float*)d_in[4];
    const float* k_scale = (const float*)d_in[5];
    const float* k_bias  = (const float*)d_in[6];
    const float* Wv      = (const float*)d_in[7];
    const float* v_scale = (const float*)d_in[8];
    const float* v_bias  = (const float*)d_in[9];
    const float* Wp      = (const float*)d_in[10];
    const float* bp      = (const float*)d_in[11];
    const float* p_scale = (const float*)d_in[12];
    const float* p_bias  = (const float*)d_in[13];
    float* out = (float*)d_out;

    __half *xsT, *qT, *ksp, *vsp, *x2T, *attnT, *wsplit;
    float *q, *k, *v, *gscale, *gbias;
    cudaGetSymbolAddress((void**)&xsT,    g_xsT);
    cudaGetSymbolAddress((void**)&q,      g_q);
    cudaGetSymbolAddress((void**)&k,      g_k);
    cudaGetSymbolAddress((void**)&v,      g_v);
    cudaGetSymbolAddress((void**)&qT,     g_qT);
    cudaGetSymbolAddress((void**)&ksp,    g_ks);
    cudaGetSymbolAddress((void**)&vsp,    g_vs);
    cudaGetSymbolAddress((void**)&x2T,    g_x2T);
    cudaGetSymbolAddress((void**)&attnT,  g_attnT);
    cudaGetSymbolAddress((void**)&wsplit, g_wsplit);
    cudaGetSymbolAddress((void**)&gscale, g_scale);
    cudaGetSymbolAddress((void**)&gbias,  g_bias);

    const int SMEM_BYTES = 2 * STAGE_BYTES;   // 73728
    cudaFuncSetAttribute(gemm_hmma_kernel<0>, cudaFuncAttributeMaxDynamicSharedMemorySize, SMEM_BYTES);
    cudaFuncSetAttribute(gemm_hmma_kernel<1>, cudaFuncAttributeMaxDynamicSharedMemorySize, SMEM_BYTES);

    // 0. weight splits (fp16 hi/mid', exact) + scale/bias concat
    wsplit_kernel<<<4096, 256>>>(Wq, Wk, Wv, Wp, wsplit);
    sb_kernel<<<6, 256>>>(q_scale, q_bias, k_scale, k_bias, v_scale, v_bias, gscale, gbias);

    // 1. shortcut LIF fused with transpose -> fp16 spikes [tb][n][c]
    lif_in_trans_kernel<<<dim3(4, 8, 32), 256>>>(x, xsT);

    // 2. q/k/v conv + BN via HMMA (exact 2-split fp16, K'=1024)
    gemm_hmma_kernel<0><<<dim3(2, 12, 128), 256, SMEM_BYTES>>>(
        wsplit, xsT, q, k, v, gscale, gbias, nullptr, nullptr, nullptr, 0);

    // 3. fused LIF on q/k/v -> fp16 spikes (+ v output transpose)
    lif_qkv_kernel<<<dim3(4, 8, 32), 256>>>(q, k, v, qT, ksp, vsp, out + TOTAL);

    // 4. attnT = (1/16) (k^T v)^T per (chunk, b, h), HMMA fp16 (exact)
    attn_hmma_kernel<<<2 * B_ * NH, 128>>>(ksp, vsp, attnT);

    // 5. x2 = attn^T @ q + LIF(0.5), HMMA fp16, writes x2T fp16 [tb][n][c]
    x2_hmma_kernel<<<dim3(2, NH, B_), 256>>>(qT, attnT, x2T);

    // 6. proj conv + BN + identity via HMMA -> out[0 : TOTAL)
    gemm_hmma_kernel<1><<<dim3(2, 4, 128), 256, SMEM_BYTES>>>(
        wsplit, x2T, nullptr, nullptr, nullptr, p_scale, p_bias, bp, x, out, 1536);
}